// round 16
// baseline (speedup 1.0000x reference)
#include <cuda_runtime.h>
#include <cuda_fp16.h>
#include <math.h>
#include <stdint.h>

// Problem constants
#define NB 4096
#define ND 128
#define EPSF 1e-8f
#define TEMPF 11.313708498984761f   // sqrt(128)

// Scratch (device globals; no allocation allowed)
__device__ __half g_qn_hi[NB * ND];
__device__ __half g_kn_hi[NB * ND];
__device__ float g_qsq[NB];
__device__ float g_ksq[NB];
__device__ float g_psum[NB * 64];   // per-(row, jblock-half) partial row sums

// ---------------------------------------------------------------------------
// PTX helpers (base compute_103 — NO sm_103a-only instructions)
// ---------------------------------------------------------------------------
__device__ __forceinline__ uint32_t smem_u32(const void* p) {
    uint32_t a;
    asm("{ .reg .u64 t; cvta.to.shared.u64 t, %1; cvt.u32.u64 %0, t; }"
        : "=r"(a) : "l"(p));
    return a;
}

__device__ __forceinline__ void ldsm4(uint32_t* r, uint32_t addr) {
    asm volatile("ldmatrix.sync.aligned.m8n8.x4.shared.b16 {%0,%1,%2,%3}, [%4];"
                 : "=r"(r[0]), "=r"(r[1]), "=r"(r[2]), "=r"(r[3]) : "r"(addr));
}

__device__ __forceinline__ void mma_f16(float* c, const uint32_t* a,
                                        const uint32_t* b) {
    asm volatile(
        "mma.sync.aligned.m16n8k16.row.col.f32.f16.f16.f32 "
        "{%0,%1,%2,%3}, {%4,%5,%6,%7}, {%8,%9}, {%0,%1,%2,%3};"
        : "+f"(c[0]), "+f"(c[1]), "+f"(c[2]), "+f"(c[3])
        : "r"(a[0]), "r"(a[1]), "r"(a[2]), "r"(a[3]), "r"(b[0]), "r"(b[1]));
}

__device__ __forceinline__ void cp16(uint32_t s, const void* g) {
    asm volatile("cp.async.cg.shared.global [%0], [%1], 16;" :: "r"(s), "l"(g));
}
__device__ __forceinline__ void cp_commit() {
    asm volatile("cp.async.commit_group;" ::: "memory");
}
__device__ __forceinline__ void cp_wait1() {
    asm volatile("cp.async.wait_group 1;" ::: "memory");
}
__device__ __forceinline__ void cp_wait0() {
    asm volatile("cp.async.wait_group 0;" ::: "memory");
}

__device__ __forceinline__ uint32_t pack_h2(__half a, __half b) {
    __half2 t(a, b);
    return *reinterpret_cast<uint32_t*>(&t);
}

// fast approx sqrt (1 MUFU op; ~2^-21 rel err; sqrt.approx(0)=0)
__device__ __forceinline__ float fsqrt_ap(float x) {
    float r;
    asm("sqrt.approx.f32 %0, %1;" : "=f"(r) : "f"(x));
    return r;
}

// ---------------------------------------------------------------------------
// Shared tile-layout constants
// ---------------------------------------------------------------------------
#define SSTRIDE 40                 // fp16 elems per smem row (80 B)
#define MAT_BYTES 10240            // 128 rows * 80 B

// ---------------------------------------------------------------------------
// Kernel A: projection via compensated HMMA + analytic metric normalization.
// 32-row tiles, grid (128,2) = 256 CTAs; 8 warps as 2(M) x 4(N), warp 16x32.
// Register double-buffered prefetch; q = Xhi*Whi + Xlo*Whi + Xhi*Wlo (+bias).
// ---------------------------------------------------------------------------
#define PROWS 32

__global__ __launch_bounds__(256) void proj_mma_kernel(
    const float* __restrict__ Xq, const float* __restrict__ Wq,
    const float* __restrict__ bq,
    const float* __restrict__ Xk, const float* __restrict__ Wk,
    const float* __restrict__ bk)
{
    __shared__ __align__(16) __half sxh[PROWS][SSTRIDE];
    __shared__ __align__(16) __half sxl[PROWS][SSTRIDE];
    __shared__ __align__(16) __half swh[128][SSTRIDE];
    __shared__ __align__(16) __half swl[128][SSTRIDE];
    __shared__ float b_s[128];
    __shared__ float red[PROWS][4];

    const int tid = threadIdx.x;
    const int lane = tid & 31;
    const int w = tid >> 5;
    const int wm = w >> 2;         // 0/1: M half (16 rows)
    const int wn = w & 3;          // 0..3: N quarter (32 cols)
    const int which = blockIdx.y;
    const int i0 = blockIdx.x * PROWS;

    const float* X = which ? Xk : Xq;
    const float* W = which ? Wk : Wq;
    if (tid < 128) b_s[tid] = which ? bk[tid] : bq[tid];

    const uint32_t a_sxh = smem_u32(sxh);
    const uint32_t a_sxl = smem_u32(sxl);
    const uint32_t a_swh = smem_u32(swh);
    const uint32_t a_swl = smem_u32(swl);

    const int xrow = tid >> 3;             // 0..31
    const int xc4 = tid & 7;

    float4 xcur, wcur[4], xnxt, wnxt[4];

    xcur = *(const float4*)&X[(size_t)(i0 + xrow) * ND + xc4 * 4];
#pragma unroll
    for (int it = 0; it < 4; it++)
        wcur[it] = *(const float4*)&W[(size_t)(it * 32 + xrow) * ND + xc4 * 4];

    float acc[4][4];
#pragma unroll
    for (int n8 = 0; n8 < 4; n8++)
#pragma unroll
        for (int q = 0; q < 4; q++) acc[n8][q] = 0.f;

    const int a_row = lane & 15;
    const int a_kh = lane >> 4;
    const int b_n = (lane & 7) | ((lane >> 1) & 8);
    const int b_kh = (lane >> 3) & 1;

    for (int kc = 0; kc < 4; kc++) {
        // prefetch next chunk
        if (kc < 3) {
            xnxt = *(const float4*)&X[(size_t)(i0 + xrow) * ND + (kc + 1) * 32 + xc4 * 4];
#pragma unroll
            for (int it = 0; it < 4; it++)
                wnxt[it] = *(const float4*)&W[(size_t)(it * 32 + xrow) * ND + (kc + 1) * 32 + xc4 * 4];
        }

        // convert current chunk into smem
        {
            const float4 v = xcur;
            const __half h0 = __float2half(v.x), h1 = __float2half(v.y);
            const __half h2 = __float2half(v.z), h3 = __float2half(v.w);
            const __half l0 = __float2half(v.x - __half2float(h0));
            const __half l1 = __float2half(v.y - __half2float(h1));
            const __half l2 = __float2half(v.z - __half2float(h2));
            const __half l3 = __float2half(v.w - __half2float(h3));
            *(uint2*)&sxh[xrow][xc4 * 4] = make_uint2(pack_h2(h0, h1), pack_h2(h2, h3));
            *(uint2*)&sxl[xrow][xc4 * 4] = make_uint2(pack_h2(l0, l1), pack_h2(l2, l3));
        }
#pragma unroll
        for (int it = 0; it < 4; it++) {
            const int row = it * 32 + xrow;
            const float4 v = wcur[it];
            const __half h0 = __float2half(v.x), h1 = __float2half(v.y);
            const __half h2 = __float2half(v.z), h3 = __float2half(v.w);
            const __half l0 = __float2half(v.x - __half2float(h0));
            const __half l1 = __float2half(v.y - __half2float(h1));
            const __half l2 = __float2half(v.z - __half2float(h2));
            const __half l3 = __float2half(v.w - __half2float(h3));
            *(uint2*)&swh[row][xc4 * 4] = make_uint2(pack_h2(h0, h1), pack_h2(h2, h3));
            *(uint2*)&swl[row][xc4 * 4] = make_uint2(pack_h2(l0, l1), pack_h2(l2, l3));
        }
        __syncthreads();

#pragma unroll
        for (int ks = 0; ks < 2; ks++) {
            const int k0 = ks * 16;
            const uint32_t a_off =
                (uint32_t)(((wm * 16 + a_row) * SSTRIDE + k0 + a_kh * 8) * 2);
            const uint32_t b_off =
                (uint32_t)(((wn * 32 + b_n) * SSTRIDE + k0 + b_kh * 8) * 2);

            uint32_t xh[4], xl[4], whr[2][4];
            ldsm4(xh, a_sxh + a_off);
            ldsm4(xl, a_sxl + a_off);

#pragma unroll
            for (int nt = 0; nt < 2; nt++) {
                ldsm4(whr[nt], a_swh + b_off + (uint32_t)(nt * 16 * SSTRIDE * 2));
                mma_f16(acc[2 * nt + 0], xh, &whr[nt][0]);
                mma_f16(acc[2 * nt + 1], xh, &whr[nt][2]);
            }
#pragma unroll
            for (int nt = 0; nt < 2; nt++) {
                mma_f16(acc[2 * nt + 0], xl, &whr[nt][0]);
                mma_f16(acc[2 * nt + 1], xl, &whr[nt][2]);
            }
#pragma unroll
            for (int nt = 0; nt < 2; nt++) {
                uint32_t wl[4];
                ldsm4(wl, a_swl + b_off + (uint32_t)(nt * 16 * SSTRIDE * 2));
                mma_f16(acc[2 * nt + 0], xh, &wl[0]);
                mma_f16(acc[2 * nt + 1], xh, &wl[2]);
            }
        }
        __syncthreads();

        xcur = xnxt;
#pragma unroll
        for (int it = 0; it < 4; it++) wcur[it] = wnxt[it];
    }

    // bias add (warp covers cols wn*32 + n8*8 + cq)
    const int cq = (lane & 3) * 2;
#pragma unroll
    for (int n8 = 0; n8 < 4; n8++) {
        const int cl = wn * 32 + n8 * 8 + cq;
        acc[n8][0] += b_s[cl];     acc[n8][1] += b_s[cl + 1];
        acc[n8][2] += b_s[cl];     acc[n8][3] += b_s[cl + 1];
    }

    // per-warp (32-col) partial row sums of squares
    float s0 = 0.f, s1 = 0.f;
#pragma unroll
    for (int n8 = 0; n8 < 4; n8++) {
        s0 += acc[n8][0] * acc[n8][0] + acc[n8][1] * acc[n8][1];
        s1 += acc[n8][2] * acc[n8][2] + acc[n8][3] * acc[n8][3];
    }
    s0 += __shfl_xor_sync(0xffffffffu, s0, 1);
    s0 += __shfl_xor_sync(0xffffffffu, s0, 2);
    s1 += __shfl_xor_sync(0xffffffffu, s1, 1);
    s1 += __shfl_xor_sync(0xffffffffu, s1, 2);

    const int rq = lane >> 2;
    const int rl0 = wm * 16 + rq;          // local rows
    const int rl1 = rl0 + 8;
    if ((lane & 3) == 0) {
        red[rl0][wn] = s0;
        red[rl1][wn] = s1;
    }
    __syncthreads();

    const float fs0 = red[rl0][0] + red[rl0][1] + red[rl0][2] + red[rl0][3];
    const float fs1 = red[rl1][0] + red[rl1][1] + red[rl1][2] + red[rl1][3];

    const float invD = 1.0f / (float)ND;
    const float fro0 = sqrtf(fs0 * fs0 * invD * invD + 2.0f * fs0 * invD + (float)ND);
    const float fro1 = sqrtf(fs1 * fs1 * invD * invD + 2.0f * fs1 * invD + (float)ND);
    const float inv0 = 1.0f / (sqrtf((fs0 * fs0 * invD + fs0) / (fro0 + EPSF)) + EPSF);
    const float inv1 = 1.0f / (sqrtf((fs1 * fs1 * invD + fs1) / (fro1 + EPSF)) + EPSF);

    const int r0 = i0 + rl0;
    const int r1 = i0 + rl1;

    if (wn == 0 && (lane & 3) == 0) {
        float* sq = which ? g_ksq : g_qsq;
        sq[r0] = fs0 * inv0 * inv0;
        sq[r1] = fs1 * inv1 * inv1;
    }

    __half* outH = which ? g_kn_hi : g_qn_hi;
#pragma unroll
    for (int n8 = 0; n8 < 4; n8++) {
        const int col = wn * 32 + n8 * 8 + cq;
        *(uint32_t*)&outH[(size_t)r0 * ND + col] =
            pack_h2(__float2half(acc[n8][0] * inv0), __float2half(acc[n8][1] * inv0));
        *(uint32_t*)&outH[(size_t)r1 * ND + col] =
            pack_h2(__float2half(acc[n8][2] * inv1), __float2half(acc[n8][3] * inv1));
    }
}

// ---------------------------------------------------------------------------
// Kernel B: single-product fp16 HMMA Gram + fused exp-logit epilogue
// (approx sqrt/div) + per-warp partial row sums into g_psum.
// Stage = 2 matrices (qn_hi, kn_hi). CTA 128x128, 8 warps (4M x 2N).
// ---------------------------------------------------------------------------
#define STAGE_BYTES (2 * MAT_BYTES)
#define GRAM_SMEM (2 * STAGE_BYTES)   // 40960

__device__ __forceinline__ void issue_chunk(uint32_t sbase, int st, int kc,
                                            int i0, int j0, int tid)
{
    const uint32_t stb = sbase + (uint32_t)(st * STAGE_BYTES);
#pragma unroll
    for (int it = 0; it < 2; it++) {
        const int t = it * 256 + tid;
        const int row = t >> 2;
        const int seg = t & 3;
        const uint32_t soff = (uint32_t)(row * 80 + seg * 16);
        const size_t gi = (size_t)(i0 + row) * ND + kc * 32 + seg * 8;
        const size_t gj = (size_t)(j0 + row) * ND + kc * 32 + seg * 8;
        cp16(stb + 0 * MAT_BYTES + soff, &g_qn_hi[gi]);
        cp16(stb + 1 * MAT_BYTES + soff, &g_kn_hi[gj]);
    }
}

__global__ __launch_bounds__(256, 2) void gram_exp_kernel(float* __restrict__ out)
{
    extern __shared__ __align__(16) char dsm[];
    __shared__ float ks_s[128];
    __shared__ float qs_s[128];

    const int tid = threadIdx.x;
    const int lane = tid & 31;
    const int w = tid >> 5;
    const int wm = w & 3;
    const int wn = w >> 2;
    const int i0 = blockIdx.y * 128;
    const int j0 = blockIdx.x * 128;

    if (tid < 128) ks_s[tid] = g_ksq[j0 + tid];
    else           qs_s[tid - 128] = g_qsq[i0 + tid - 128];

    const uint32_t sbase = smem_u32(dsm);

    issue_chunk(sbase, 0, 0, i0, j0, tid); cp_commit();
    issue_chunk(sbase, 1, 1, i0, j0, tid); cp_commit();

    float acc[2][8][4];
#pragma unroll
    for (int mt = 0; mt < 2; mt++)
#pragma unroll
        for (int n8 = 0; n8 < 8; n8++)
#pragma unroll
            for (int q = 0; q < 4; q++) acc[mt][n8][q] = 0.f;

    const int a_row = lane & 15;
    const int a_kh = lane >> 4;
    const int b_n = (lane & 7) | ((lane >> 1) & 8);
    const int b_kh = (lane >> 3) & 1;

#pragma unroll
    for (int kc = 0; kc < 4; kc++) {
        if (kc < 3) cp_wait1(); else cp_wait0();
        __syncthreads();

        const uint32_t stb = sbase + (uint32_t)((kc & 1) * STAGE_BYTES);
        const uint32_t ashi = stb + 0 * MAT_BYTES;
        const uint32_t bshi = stb + 1 * MAT_BYTES;

#pragma unroll
        for (int ks = 0; ks < 2; ks++) {
            const int k0 = ks * 16;
            const uint32_t a_off =
                (uint32_t)(((wm * 32 + a_row) * SSTRIDE + k0 + a_kh * 8) * 2);
            const uint32_t b_off0 =
                (uint32_t)(((wn * 64 + b_n) * SSTRIDE + k0 + b_kh * 8) * 2);

            uint32_t ahi[2][4], bf[4][4];
#pragma unroll
            for (int mt = 0; mt < 2; mt++)
                ldsm4(ahi[mt], ashi + a_off + (uint32_t)(mt * 16 * SSTRIDE * 2));
#pragma unroll
            for (int nt = 0; nt < 4; nt++)
                ldsm4(bf[nt], bshi + b_off0 + (uint32_t)(nt * 16 * SSTRIDE * 2));

#pragma unroll
            for (int mt = 0; mt < 2; mt++)
#pragma unroll
                for (int nt = 0; nt < 4; nt++) {
                    mma_f16(acc[mt][nt * 2 + 0], ahi[mt], &bf[nt][0]);
                    mma_f16(acc[mt][nt * 2 + 1], ahi[mt], &bf[nt][2]);
                }
        }
        __syncthreads();
        if (kc < 2) { issue_chunk(sbase, kc & 1, kc + 2, i0, j0, tid); cp_commit(); }
    }

    // Epilogue + partial row sums (approx math).
    const int rq = lane >> 2;
    const int cq = (lane & 3) * 2;
    float rs[2][2];
    rs[0][0] = rs[0][1] = rs[1][0] = rs[1][1] = 0.f;

#pragma unroll
    for (int mt = 0; mt < 2; mt++) {
        const int rl0 = wm * 32 + mt * 16 + rq;
        const float qs0 = qs_s[rl0];
        const float qs1 = qs_s[rl0 + 8];
#pragma unroll
        for (int n8 = 0; n8 < 8; n8++) {
            const int cl = wn * 64 + n8 * 8 + cq;
            const float k0v = ks_s[cl], k1v = ks_s[cl + 1];
            const float* a = acc[mt][n8];

            float d00 = fmaxf(qs0 + k0v - 2.0f * a[0], 0.0f);
            float d01 = fmaxf(qs0 + k1v - 2.0f * a[1], 0.0f);
            float d10 = fmaxf(qs1 + k0v - 2.0f * a[2], 0.0f);
            float d11 = fmaxf(qs1 + k1v - 2.0f * a[3], 0.0f);

            float2 e0, e1;
            e0.x = __expf(__fdividef(TEMPF, 1.0f + fsqrt_ap(d00)));
            e0.y = __expf(__fdividef(TEMPF, 1.0f + fsqrt_ap(d01)));
            e1.x = __expf(__fdividef(TEMPF, 1.0f + fsqrt_ap(d10)));
            e1.y = __expf(__fdividef(TEMPF, 1.0f + fsqrt_ap(d11)));

            rs[mt][0] += e0.x + e0.y;
            rs[mt][1] += e1.x + e1.y;

            *(float2*)&out[(size_t)(i0 + rl0) * NB + j0 + cl] = e0;
            *(float2*)&out[(size_t)(i0 + rl0 + 8) * NB + j0 + cl] = e1;
        }
    }

    // Reduce partial sums over the 4 lanes sharing a row; store to g_psum.
#pragma unroll
    for (int mt = 0; mt < 2; mt++)
#pragma unroll
        for (int h = 0; h < 2; h++) {
            float s = rs[mt][h];
            s += __shfl_xor_sync(0xffffffffu, s, 1);
            s += __shfl_xor_sync(0xffffffffu, s, 2);
            if ((lane & 3) == 0) {
                const int row = i0 + wm * 32 + mt * 16 + rq + h * 8;
                g_psum[(size_t)row * 64 + blockIdx.x * 2 + wn] = s;
            }
        }
}

// ---------------------------------------------------------------------------
// Kernel C: normalize rows using precomputed partial sums.
// Half-row blocks: 8192 blocks x 256 threads x 2 float4.
// ---------------------------------------------------------------------------
__global__ __launch_bounds__(256) void scale_kernel(float* __restrict__ out)
{
    __shared__ float sinv;
    const int tid = threadIdx.x;
    const int row = blockIdx.x >> 1;
    const int half = blockIdx.x & 1;

    float4* p = (float4*)(out + (size_t)row * NB + half * 2048);
    float4 v0 = p[tid];
    float4 v1 = p[tid + 256];

    if (tid < 32) {
        float s = g_psum[(size_t)row * 64 + tid] + g_psum[(size_t)row * 64 + 32 + tid];
#pragma unroll
        for (int o = 16; o > 0; o >>= 1) s += __shfl_xor_sync(0xffffffffu, s, o);
        if (tid == 0) sinv = 1.0f / s;
    }
    __syncthreads();
    const float inv = sinv;

    v0.x *= inv; v0.y *= inv; v0.z *= inv; v0.w *= inv;
    v1.x *= inv; v1.y *= inv; v1.z *= inv; v1.w *= inv;
    p[tid] = v0;
    p[tid + 256] = v1;
}

// ---------------------------------------------------------------------------
// Launch
// ---------------------------------------------------------------------------
extern "C" void kernel_launch(void* const* d_in, const int* in_sizes, int n_in,
                              void* d_out, int out_size)
{
    (void)in_sizes; (void)n_in; (void)out_size;
    const float* qp = (const float*)d_in[0];
    const float* kp = (const float*)d_in[1];
    const float* Wq = (const float*)d_in[2];
    const float* bq = (const float*)d_in[3];
    const float* Wk = (const float*)d_in[4];
    const float* bk = (const float*)d_in[5];
    float* out = (float*)d_out;

    cudaFuncSetAttribute(gram_exp_kernel,
                         cudaFuncAttributeMaxDynamicSharedMemorySize, GRAM_SMEM);

    dim3 gp(NB / PROWS, 2);
    proj_mma_kernel<<<gp, 256>>>(qp, Wq, bq, kp, Wk, bk);

    dim3 g(NB / 128, NB / 128);
    gram_exp_kernel<<<g, 256, GRAM_SMEM>>>(out);

    scale_kernel<<<NB * 2, 256>>>(out);
}

// round 17
// speedup vs baseline: 1.0249x; 1.0249x over previous
#include <cuda_runtime.h>
#include <cuda_fp16.h>
#include <math.h>
#include <stdint.h>

// Problem constants
#define NB 4096
#define ND 128
#define EPSF 1e-8f
#define TEMPF 11.313708498984761f   // sqrt(128)

// Scratch (device globals; no allocation allowed)
__device__ __half g_qn_hi[NB * ND];
__device__ __half g_kn_hi[NB * ND];
__device__ float g_qsq[NB];
__device__ float g_ksq[NB];
__device__ float g_psum[NB * 64];   // per-(row, jblock-half) partial row sums
__device__ __half g_e[NB * NB];     // shifted exp values (fp16 staging)

// ---------------------------------------------------------------------------
// PTX helpers (base compute_103 — NO sm_103a-only instructions)
// ---------------------------------------------------------------------------
__device__ __forceinline__ uint32_t smem_u32(const void* p) {
    uint32_t a;
    asm("{ .reg .u64 t; cvta.to.shared.u64 t, %1; cvt.u32.u64 %0, t; }"
        : "=r"(a) : "l"(p));
    return a;
}

__device__ __forceinline__ void ldsm4(uint32_t* r, uint32_t addr) {
    asm volatile("ldmatrix.sync.aligned.m8n8.x4.shared.b16 {%0,%1,%2,%3}, [%4];"
                 : "=r"(r[0]), "=r"(r[1]), "=r"(r[2]), "=r"(r[3]) : "r"(addr));
}

__device__ __forceinline__ void mma_f16(float* c, const uint32_t* a,
                                        const uint32_t* b) {
    asm volatile(
        "mma.sync.aligned.m16n8k16.row.col.f32.f16.f16.f32 "
        "{%0,%1,%2,%3}, {%4,%5,%6,%7}, {%8,%9}, {%0,%1,%2,%3};"
        : "+f"(c[0]), "+f"(c[1]), "+f"(c[2]), "+f"(c[3])
        : "r"(a[0]), "r"(a[1]), "r"(a[2]), "r"(a[3]), "r"(b[0]), "r"(b[1]));
}

__device__ __forceinline__ void cp16(uint32_t s, const void* g) {
    asm volatile("cp.async.cg.shared.global [%0], [%1], 16;" :: "r"(s), "l"(g));
}
__device__ __forceinline__ void cp_commit() {
    asm volatile("cp.async.commit_group;" ::: "memory");
}
__device__ __forceinline__ void cp_wait1() {
    asm volatile("cp.async.wait_group 1;" ::: "memory");
}
__device__ __forceinline__ void cp_wait0() {
    asm volatile("cp.async.wait_group 0;" ::: "memory");
}

__device__ __forceinline__ uint32_t pack_h2(__half a, __half b) {
    __half2 t(a, b);
    return *reinterpret_cast<uint32_t*>(&t);
}

// fast approx sqrt (1 MUFU op; ~2^-21 rel err; sqrt.approx(0)=0)
__device__ __forceinline__ float fsqrt_ap(float x) {
    float r;
    asm("sqrt.approx.f32 %0, %1;" : "=f"(r) : "f"(x));
    return r;
}

// ---------------------------------------------------------------------------
// Shared tile-layout constants
// ---------------------------------------------------------------------------
#define SSTRIDE 40                 // fp16 elems per smem row (80 B)
#define MAT_BYTES 10240            // 128 rows * 80 B

// ---------------------------------------------------------------------------
// Kernel A: projection via compensated HMMA + analytic metric normalization.
// 32-row tiles, grid (128,2) = 256 CTAs; 8 warps as 2(M) x 4(N), warp 16x32.
// Register double-buffered prefetch; q = Xhi*Whi + Xlo*Whi + Xhi*Wlo (+bias).
// ---------------------------------------------------------------------------
#define PROWS 32

__global__ __launch_bounds__(256) void proj_mma_kernel(
    const float* __restrict__ Xq, const float* __restrict__ Wq,
    const float* __restrict__ bq,
    const float* __restrict__ Xk, const float* __restrict__ Wk,
    const float* __restrict__ bk)
{
    __shared__ __align__(16) __half sxh[PROWS][SSTRIDE];
    __shared__ __align__(16) __half sxl[PROWS][SSTRIDE];
    __shared__ __align__(16) __half swh[128][SSTRIDE];
    __shared__ __align__(16) __half swl[128][SSTRIDE];
    __shared__ float b_s[128];
    __shared__ float red[PROWS][4];

    const int tid = threadIdx.x;
    const int lane = tid & 31;
    const int w = tid >> 5;
    const int wm = w >> 2;         // 0/1: M half (16 rows)
    const int wn = w & 3;          // 0..3: N quarter (32 cols)
    const int which = blockIdx.y;
    const int i0 = blockIdx.x * PROWS;

    const float* X = which ? Xk : Xq;
    const float* W = which ? Wk : Wq;
    if (tid < 128) b_s[tid] = which ? bk[tid] : bq[tid];

    const uint32_t a_sxh = smem_u32(sxh);
    const uint32_t a_sxl = smem_u32(sxl);
    const uint32_t a_swh = smem_u32(swh);
    const uint32_t a_swl = smem_u32(swl);

    const int xrow = tid >> 3;             // 0..31
    const int xc4 = tid & 7;

    float4 xcur, wcur[4], xnxt, wnxt[4];

    xcur = *(const float4*)&X[(size_t)(i0 + xrow) * ND + xc4 * 4];
#pragma unroll
    for (int it = 0; it < 4; it++)
        wcur[it] = *(const float4*)&W[(size_t)(it * 32 + xrow) * ND + xc4 * 4];

    float acc[4][4];
#pragma unroll
    for (int n8 = 0; n8 < 4; n8++)
#pragma unroll
        for (int q = 0; q < 4; q++) acc[n8][q] = 0.f;

    const int a_row = lane & 15;
    const int a_kh = lane >> 4;
    const int b_n = (lane & 7) | ((lane >> 1) & 8);
    const int b_kh = (lane >> 3) & 1;

    for (int kc = 0; kc < 4; kc++) {
        // prefetch next chunk
        if (kc < 3) {
            xnxt = *(const float4*)&X[(size_t)(i0 + xrow) * ND + (kc + 1) * 32 + xc4 * 4];
#pragma unroll
            for (int it = 0; it < 4; it++)
                wnxt[it] = *(const float4*)&W[(size_t)(it * 32 + xrow) * ND + (kc + 1) * 32 + xc4 * 4];
        }

        // convert current chunk into smem
        {
            const float4 v = xcur;
            const __half h0 = __float2half(v.x), h1 = __float2half(v.y);
            const __half h2 = __float2half(v.z), h3 = __float2half(v.w);
            const __half l0 = __float2half(v.x - __half2float(h0));
            const __half l1 = __float2half(v.y - __half2float(h1));
            const __half l2 = __float2half(v.z - __half2float(h2));
            const __half l3 = __float2half(v.w - __half2float(h3));
            *(uint2*)&sxh[xrow][xc4 * 4] = make_uint2(pack_h2(h0, h1), pack_h2(h2, h3));
            *(uint2*)&sxl[xrow][xc4 * 4] = make_uint2(pack_h2(l0, l1), pack_h2(l2, l3));
        }
#pragma unroll
        for (int it = 0; it < 4; it++) {
            const int row = it * 32 + xrow;
            const float4 v = wcur[it];
            const __half h0 = __float2half(v.x), h1 = __float2half(v.y);
            const __half h2 = __float2half(v.z), h3 = __float2half(v.w);
            const __half l0 = __float2half(v.x - __half2float(h0));
            const __half l1 = __float2half(v.y - __half2float(h1));
            const __half l2 = __float2half(v.z - __half2float(h2));
            const __half l3 = __float2half(v.w - __half2float(h3));
            *(uint2*)&swh[row][xc4 * 4] = make_uint2(pack_h2(h0, h1), pack_h2(h2, h3));
            *(uint2*)&swl[row][xc4 * 4] = make_uint2(pack_h2(l0, l1), pack_h2(l2, l3));
        }
        __syncthreads();

#pragma unroll
        for (int ks = 0; ks < 2; ks++) {
            const int k0 = ks * 16;
            const uint32_t a_off =
                (uint32_t)(((wm * 16 + a_row) * SSTRIDE + k0 + a_kh * 8) * 2);
            const uint32_t b_off =
                (uint32_t)(((wn * 32 + b_n) * SSTRIDE + k0 + b_kh * 8) * 2);

            uint32_t xh[4], xl[4], whr[2][4];
            ldsm4(xh, a_sxh + a_off);
            ldsm4(xl, a_sxl + a_off);

#pragma unroll
            for (int nt = 0; nt < 2; nt++) {
                ldsm4(whr[nt], a_swh + b_off + (uint32_t)(nt * 16 * SSTRIDE * 2));
                mma_f16(acc[2 * nt + 0], xh, &whr[nt][0]);
                mma_f16(acc[2 * nt + 1], xh, &whr[nt][2]);
            }
#pragma unroll
            for (int nt = 0; nt < 2; nt++) {
                mma_f16(acc[2 * nt + 0], xl, &whr[nt][0]);
                mma_f16(acc[2 * nt + 1], xl, &whr[nt][2]);
            }
#pragma unroll
            for (int nt = 0; nt < 2; nt++) {
                uint32_t wl[4];
                ldsm4(wl, a_swl + b_off + (uint32_t)(nt * 16 * SSTRIDE * 2));
                mma_f16(acc[2 * nt + 0], xh, &wl[0]);
                mma_f16(acc[2 * nt + 1], xh, &wl[2]);
            }
        }
        __syncthreads();

        xcur = xnxt;
#pragma unroll
        for (int it = 0; it < 4; it++) wcur[it] = wnxt[it];
    }

    // bias add (warp covers cols wn*32 + n8*8 + cq)
    const int cq = (lane & 3) * 2;
#pragma unroll
    for (int n8 = 0; n8 < 4; n8++) {
        const int cl = wn * 32 + n8 * 8 + cq;
        acc[n8][0] += b_s[cl];     acc[n8][1] += b_s[cl + 1];
        acc[n8][2] += b_s[cl];     acc[n8][3] += b_s[cl + 1];
    }

    // per-warp (32-col) partial row sums of squares
    float s0 = 0.f, s1 = 0.f;
#pragma unroll
    for (int n8 = 0; n8 < 4; n8++) {
        s0 += acc[n8][0] * acc[n8][0] + acc[n8][1] * acc[n8][1];
        s1 += acc[n8][2] * acc[n8][2] + acc[n8][3] * acc[n8][3];
    }
    s0 += __shfl_xor_sync(0xffffffffu, s0, 1);
    s0 += __shfl_xor_sync(0xffffffffu, s0, 2);
    s1 += __shfl_xor_sync(0xffffffffu, s1, 1);
    s1 += __shfl_xor_sync(0xffffffffu, s1, 2);

    const int rq = lane >> 2;
    const int rl0 = wm * 16 + rq;          // local rows
    const int rl1 = rl0 + 8;
    if ((lane & 3) == 0) {
        red[rl0][wn] = s0;
        red[rl1][wn] = s1;
    }
    __syncthreads();

    const float fs0 = red[rl0][0] + red[rl0][1] + red[rl0][2] + red[rl0][3];
    const float fs1 = red[rl1][0] + red[rl1][1] + red[rl1][2] + red[rl1][3];

    const float invD = 1.0f / (float)ND;
    const float fro0 = sqrtf(fs0 * fs0 * invD * invD + 2.0f * fs0 * invD + (float)ND);
    const float fro1 = sqrtf(fs1 * fs1 * invD * invD + 2.0f * fs1 * invD + (float)ND);
    const float inv0 = 1.0f / (sqrtf((fs0 * fs0 * invD + fs0) / (fro0 + EPSF)) + EPSF);
    const float inv1 = 1.0f / (sqrtf((fs1 * fs1 * invD + fs1) / (fro1 + EPSF)) + EPSF);

    const int r0 = i0 + rl0;
    const int r1 = i0 + rl1;

    if (wn == 0 && (lane & 3) == 0) {
        float* sq = which ? g_ksq : g_qsq;
        sq[r0] = fs0 * inv0 * inv0;
        sq[r1] = fs1 * inv1 * inv1;
    }

    __half* outH = which ? g_kn_hi : g_qn_hi;
#pragma unroll
    for (int n8 = 0; n8 < 4; n8++) {
        const int col = wn * 32 + n8 * 8 + cq;
        *(uint32_t*)&outH[(size_t)r0 * ND + col] =
            pack_h2(__float2half(acc[n8][0] * inv0), __float2half(acc[n8][1] * inv0));
        *(uint32_t*)&outH[(size_t)r1 * ND + col] =
            pack_h2(__float2half(acc[n8][2] * inv1), __float2half(acc[n8][3] * inv1));
    }
}

// ---------------------------------------------------------------------------
// Kernel B: single-product fp16 HMMA Gram + fused shifted-exp epilogue.
// Stores e = exp(logit - TEMPF) as packed fp16 into g_e (shift cancels in
// normalization; range (5e-4, 1] fits fp16), plus fp32 partial row sums.
// ---------------------------------------------------------------------------
#define STAGE_BYTES (2 * MAT_BYTES)
#define GRAM_SMEM (2 * STAGE_BYTES)   // 40960

__device__ __forceinline__ void issue_chunk(uint32_t sbase, int st, int kc,
                                            int i0, int j0, int tid)
{
    const uint32_t stb = sbase + (uint32_t)(st * STAGE_BYTES);
#pragma unroll
    for (int it = 0; it < 2; it++) {
        const int t = it * 256 + tid;
        const int row = t >> 2;
        const int seg = t & 3;
        const uint32_t soff = (uint32_t)(row * 80 + seg * 16);
        const size_t gi = (size_t)(i0 + row) * ND + kc * 32 + seg * 8;
        const size_t gj = (size_t)(j0 + row) * ND + kc * 32 + seg * 8;
        cp16(stb + 0 * MAT_BYTES + soff, &g_qn_hi[gi]);
        cp16(stb + 1 * MAT_BYTES + soff, &g_kn_hi[gj]);
    }
}

__global__ __launch_bounds__(256, 2) void gram_exp_kernel()
{
    extern __shared__ __align__(16) char dsm[];
    __shared__ float ks_s[128];
    __shared__ float qs_s[128];

    const int tid = threadIdx.x;
    const int lane = tid & 31;
    const int w = tid >> 5;
    const int wm = w & 3;
    const int wn = w >> 2;
    const int i0 = blockIdx.y * 128;
    const int j0 = blockIdx.x * 128;

    if (tid < 128) ks_s[tid] = g_ksq[j0 + tid];
    else           qs_s[tid - 128] = g_qsq[i0 + tid - 128];

    const uint32_t sbase = smem_u32(dsm);

    issue_chunk(sbase, 0, 0, i0, j0, tid); cp_commit();
    issue_chunk(sbase, 1, 1, i0, j0, tid); cp_commit();

    float acc[2][8][4];
#pragma unroll
    for (int mt = 0; mt < 2; mt++)
#pragma unroll
        for (int n8 = 0; n8 < 8; n8++)
#pragma unroll
            for (int q = 0; q < 4; q++) acc[mt][n8][q] = 0.f;

    const int a_row = lane & 15;
    const int a_kh = lane >> 4;
    const int b_n = (lane & 7) | ((lane >> 1) & 8);
    const int b_kh = (lane >> 3) & 1;

#pragma unroll
    for (int kc = 0; kc < 4; kc++) {
        if (kc < 3) cp_wait1(); else cp_wait0();
        __syncthreads();

        const uint32_t stb = sbase + (uint32_t)((kc & 1) * STAGE_BYTES);
        const uint32_t ashi = stb + 0 * MAT_BYTES;
        const uint32_t bshi = stb + 1 * MAT_BYTES;

#pragma unroll
        for (int ks = 0; ks < 2; ks++) {
            const int k0 = ks * 16;
            const uint32_t a_off =
                (uint32_t)(((wm * 32 + a_row) * SSTRIDE + k0 + a_kh * 8) * 2);
            const uint32_t b_off0 =
                (uint32_t)(((wn * 64 + b_n) * SSTRIDE + k0 + b_kh * 8) * 2);

            uint32_t ahi[2][4], bf[4][4];
#pragma unroll
            for (int mt = 0; mt < 2; mt++)
                ldsm4(ahi[mt], ashi + a_off + (uint32_t)(mt * 16 * SSTRIDE * 2));
#pragma unroll
            for (int nt = 0; nt < 4; nt++)
                ldsm4(bf[nt], bshi + b_off0 + (uint32_t)(nt * 16 * SSTRIDE * 2));

#pragma unroll
            for (int mt = 0; mt < 2; mt++)
#pragma unroll
                for (int nt = 0; nt < 4; nt++) {
                    mma_f16(acc[mt][nt * 2 + 0], ahi[mt], &bf[nt][0]);
                    mma_f16(acc[mt][nt * 2 + 1], ahi[mt], &bf[nt][2]);
                }
        }
        __syncthreads();
        if (kc < 2) { issue_chunk(sbase, kc & 1, kc + 2, i0, j0, tid); cp_commit(); }
    }

    // Epilogue: shifted exp -> packed fp16 store + fp32 partial row sums.
    const int rq = lane >> 2;
    const int cq = (lane & 3) * 2;
    float rs[2][2];
    rs[0][0] = rs[0][1] = rs[1][0] = rs[1][1] = 0.f;

#pragma unroll
    for (int mt = 0; mt < 2; mt++) {
        const int rl0 = wm * 32 + mt * 16 + rq;
        const float qs0 = qs_s[rl0];
        const float qs1 = qs_s[rl0 + 8];
#pragma unroll
        for (int n8 = 0; n8 < 8; n8++) {
            const int cl = wn * 64 + n8 * 8 + cq;
            const float k0v = ks_s[cl], k1v = ks_s[cl + 1];
            const float* a = acc[mt][n8];

            float d00 = fmaxf(qs0 + k0v - 2.0f * a[0], 0.0f);
            float d01 = fmaxf(qs0 + k1v - 2.0f * a[1], 0.0f);
            float d10 = fmaxf(qs1 + k0v - 2.0f * a[2], 0.0f);
            float d11 = fmaxf(qs1 + k1v - 2.0f * a[3], 0.0f);

            const float e00 = __expf(__fdividef(TEMPF, 1.0f + fsqrt_ap(d00)) - TEMPF);
            const float e01 = __expf(__fdividef(TEMPF, 1.0f + fsqrt_ap(d01)) - TEMPF);
            const float e10 = __expf(__fdividef(TEMPF, 1.0f + fsqrt_ap(d10)) - TEMPF);
            const float e11 = __expf(__fdividef(TEMPF, 1.0f + fsqrt_ap(d11)) - TEMPF);

            rs[mt][0] += e00 + e01;
            rs[mt][1] += e10 + e11;

            *(uint32_t*)&g_e[(size_t)(i0 + rl0) * NB + j0 + cl] =
                pack_h2(__float2half(e00), __float2half(e01));
            *(uint32_t*)&g_e[(size_t)(i0 + rl0 + 8) * NB + j0 + cl] =
                pack_h2(__float2half(e10), __float2half(e11));
        }
    }

    // Reduce partial sums over the 4 lanes sharing a row; store to g_psum.
#pragma unroll
    for (int mt = 0; mt < 2; mt++)
#pragma unroll
        for (int h = 0; h < 2; h++) {
            float s = rs[mt][h];
            s += __shfl_xor_sync(0xffffffffu, s, 1);
            s += __shfl_xor_sync(0xffffffffu, s, 2);
            if ((lane & 3) == 0) {
                const int row = i0 + wm * 32 + mt * 16 + rq + h * 8;
                g_psum[(size_t)row * 64 + blockIdx.x * 2 + wn] = s;
            }
        }
}

// ---------------------------------------------------------------------------
// Kernel C: normalize rows: fully coalesced fp16 read -> fp32 write.
// One row per block, 256 threads; thread t handles elements at index
// (t + q*256)*4 .. +3 for q = 0..3 — reads uint2 (4 halves) and writes
// float4 at the SAME flat index: both sides coalesced.
// ---------------------------------------------------------------------------
__global__ __launch_bounds__(256) void scale_kernel(float* __restrict__ out)
{
    __shared__ float sinv;
    const int tid = threadIdx.x;
    const int row = blockIdx.x;

    const uint2* ph = (const uint2*)(g_e + (size_t)row * NB);
    uint2 hv[4];
#pragma unroll
    for (int q = 0; q < 4; q++) hv[q] = ph[tid + q * 256];

    if (tid < 32) {
        float s = g_psum[(size_t)row * 64 + tid] + g_psum[(size_t)row * 64 + 32 + tid];
#pragma unroll
        for (int o = 16; o > 0; o >>= 1) s += __shfl_xor_sync(0xffffffffu, s, o);
        if (tid == 0) sinv = 1.0f / s;
    }
    __syncthreads();
    const float inv = sinv;

    float4* p = (float4*)(out + (size_t)row * NB);
#pragma unroll
    for (int q = 0; q < 4; q++) {
        const __half2 h01 = *(const __half2*)&hv[q].x;
        const __half2 h23 = *(const __half2*)&hv[q].y;
        const float2 f01 = __half22float2(h01);
        const float2 f23 = __half22float2(h23);
        p[tid + q * 256] = make_float4(f01.x * inv, f01.y * inv,
                                       f23.x * inv, f23.y * inv);
    }
}

// ---------------------------------------------------------------------------
// Launch
// ---------------------------------------------------------------------------
extern "C" void kernel_launch(void* const* d_in, const int* in_sizes, int n_in,
                              void* d_out, int out_size)
{
    (void)in_sizes; (void)n_in; (void)out_size;
    const float* qp = (const float*)d_in[0];
    const float* kp = (const float*)d_in[1];
    const float* Wq = (const float*)d_in[2];
    const float* bq = (const float*)d_in[3];
    const float* Wk = (const float*)d_in[4];
    const float* bk = (const float*)d_in[5];
    float* out = (float*)d_out;

    cudaFuncSetAttribute(gram_exp_kernel,
                         cudaFuncAttributeMaxDynamicSharedMemorySize, GRAM_SMEM);

    dim3 gp(NB / PROWS, 2);
    proj_mma_kernel<<<gp, 256>>>(qp, Wq, bq, kp, Wk, bk);

    dim3 g(NB / 128, NB / 128);
    gram_exp_kernel<<<g, 256, GRAM_SMEM>>>();

    scale_kernel<<<NB, 256>>>(out);
}